// round 16
// baseline (speedup 1.0000x reference)
#include <cuda_runtime.h>
#include <cuda_bf16.h>
#include <math.h>

#define B_ 64
#define W_ 4096
#define H_ 128
#define I_ 128
#define CHUNKS 8
#define TPB (W_ / CHUNKS)
#define WARPS 8
#define ROWS_PER_WARP (TPB / WARPS)

__device__ float g_pm[B_ * CHUNKS];
__device__ float g_pl[B_ * CHUNKS];
__device__ float g_pacc[B_ * CHUNKS * H_];

__device__ __forceinline__ float warp_sum(float v) {
    #pragma unroll
    for (int o = 16; o; o >>= 1) v += __shfl_xor_sync(0xffffffffu, v, o);
    return v;
}

__device__ __forceinline__ float sigm(float x) { return 1.0f / (1.0f + expf(-x)); }

// ---------------------------------------------------------------------------
// Phase 1: fused score + online-softmax weighted accumulate (1 encoder pass).
// v3 (Round-11 winner, unchanged): 4 rows/iter, __ldcs streaming.
// ---------------------------------------------------------------------------
__global__ __launch_bounds__(256, 4)
void attn_partial_kernel(const float* __restrict__ enc,
                         const float* __restrict__ h0,
                         const float* __restrict__ c0,
                         const float* __restrict__ attW,
                         const float* __restrict__ attB)
{
    const int c    = blockIdx.x;
    const int b    = blockIdx.y;
    const int tid  = threadIdx.x;
    const int warp = tid >> 5;
    const int lane = tid & 31;

    __shared__ float s_red[WARPS];
    __shared__ float s_bias;
    __shared__ float s_m[WARPS], s_l[WARPS];
    __shared__ float s_acc[WARPS][H_];

    float part = 0.f;
    if (tid < H_) {
        float hs = h0[(1 * B_ + b) * H_ + tid];
        float cs = c0[(1 * B_ + b) * H_ + tid];
        part = hs * cs * attW[H_ + tid];
    }
    part = warp_sum(part);
    if (lane == 0) s_red[warp] = part;
    __syncthreads();
    if (tid == 0) {
        float s = 0.f;
        #pragma unroll
        for (int w = 0; w < WARPS; w++) s += s_red[w];
        s_bias = s + attB[0];
    }
    __syncthreads();
    const float bias = s_bias;

    const float4 wa = *reinterpret_cast<const float4*>(attW + lane * 4);

    const int rowStart = c * TPB + warp * ROWS_PER_WARP;
    const float* encb = enc + (size_t)b * W_ * H_;

    float prevLogit;
    if (rowStart == 0) {
        prevLogit = 0.0f;
    } else {
        float4 v = __ldcs(reinterpret_cast<const float4*>(
            encb + (size_t)(rowStart - 1) * H_ + lane * 4));
        float d = v.x * wa.x + v.y * wa.y + v.z * wa.z + v.w * wa.w;
        d = warp_sum(d);
        prevLogit = d + bias;
    }

    float m = -1e30f, l = 0.f;
    float ax = 0.f, ay = 0.f, az = 0.f, aw = 0.f;

    const float* rp = encb + (size_t)rowStart * H_ + lane * 4;
    #pragma unroll 2
    for (int it = 0; it < ROWS_PER_WARP / 4; it++) {
        const float4 v0 = __ldcs(reinterpret_cast<const float4*>(rp));
        const float4 v1 = __ldcs(reinterpret_cast<const float4*>(rp + H_));
        const float4 v2 = __ldcs(reinterpret_cast<const float4*>(rp + 2 * H_));
        const float4 v3 = __ldcs(reinterpret_cast<const float4*>(rp + 3 * H_));
        rp += 4 * H_;
        float d0 = v0.x * wa.x + v0.y * wa.y + v0.z * wa.z + v0.w * wa.w;
        float d1 = v1.x * wa.x + v1.y * wa.y + v1.z * wa.z + v1.w * wa.w;
        float d2 = v2.x * wa.x + v2.y * wa.y + v2.z * wa.z + v2.w * wa.w;
        float d3 = v3.x * wa.x + v3.y * wa.y + v3.z * wa.z + v3.w * wa.w;
        #pragma unroll
        for (int o = 16; o; o >>= 1) {
            d0 += __shfl_xor_sync(0xffffffffu, d0, o);
            d1 += __shfl_xor_sync(0xffffffffu, d1, o);
            d2 += __shfl_xor_sync(0xffffffffu, d2, o);
            d3 += __shfl_xor_sync(0xffffffffu, d3, o);
        }
        const float l0 = prevLogit;
        const float l1 = d0 + bias;
        const float l2 = d1 + bias;
        const float l3 = d2 + bias;
        prevLogit = d3 + bias;
        const float mNew = fmaxf(fmaxf(m, fmaxf(l0, l1)), fmaxf(l2, l3));
        const float corr = __expf(m - mNew);
        const float p0   = __expf(l0 - mNew);
        const float p1   = __expf(l1 - mNew);
        const float p2   = __expf(l2 - mNew);
        const float p3   = __expf(l3 - mNew);
        l  = l * corr + p0 + p1 + p2 + p3;
        ax = ax * corr + p0 * v0.x + p1 * v1.x + p2 * v2.x + p3 * v3.x;
        ay = ay * corr + p0 * v0.y + p1 * v1.y + p2 * v2.y + p3 * v3.y;
        az = az * corr + p0 * v0.z + p1 * v1.z + p2 * v2.z + p3 * v3.z;
        aw = aw * corr + p0 * v0.w + p1 * v1.w + p2 * v2.w + p3 * v3.w;
        m = mNew;
    }

    if (lane == 0) { s_m[warp] = m; s_l[warp] = l; }
    s_acc[warp][lane * 4 + 0] = ax;
    s_acc[warp][lane * 4 + 1] = ay;
    s_acc[warp][lane * 4 + 2] = az;
    s_acc[warp][lane * 4 + 3] = aw;
    __syncthreads();

    if (tid < H_) {
        float M = s_m[0];
        #pragma unroll
        for (int w = 1; w < WARPS; w++) M = fmaxf(M, s_m[w]);
        float L = 0.f, A = 0.f;
        #pragma unroll
        for (int w = 0; w < WARPS; w++) {
            const float e = __expf(s_m[w] - M);
            L += s_l[w] * e;
            A += s_acc[w][tid] * e;
        }
        const int pi = b * CHUNKS + c;
        g_pacc[pi * H_ + tid] = A;
        if (tid == 0) { g_pm[pi] = M; g_pl[pi] = L; }
    }
}

// ---------------------------------------------------------------------------
// Per-batch fused tail: block = one batch, 512 threads (16 warps).
// Warp-per-output-row GEMV: weight rows read COALESCED (2 float4/lane),
// activations are smem vectors, 5-SHFL reduction per row.
// No grid barriers, no transposed staging, no cross-block traffic.
// out layout: [h2 (B,H)] [h1] [h2] [c1] [c2]
// ---------------------------------------------------------------------------
__device__ __forceinline__ float dot8_acc(const float4 w0, const float4 w1,
                                          const float4 a0, const float4 a1) {
    float acc;
    acc = w0.x * a0.x;
    acc = fmaf(w0.y, a0.y, acc);
    acc = fmaf(w0.z, a0.z, acc);
    acc = fmaf(w0.w, a0.w, acc);
    acc = fmaf(w1.x, a1.x, acc);
    acc = fmaf(w1.y, a1.y, acc);
    acc = fmaf(w1.z, a1.z, acc);
    acc = fmaf(w1.w, a1.w, acc);
    return acc;
}

// One LSTM layer for one batch row. sx = x vector (smem, H_), sh = h vector.
__device__ __forceinline__ void lstm_layer(
    int tid, int warp, int lane,
    const float* __restrict__ sx, const float* __restrict__ sh,
    const float* __restrict__ W_ih, const float* __restrict__ W_hh,
    const float* __restrict__ b_ih, const float* __restrict__ b_hh,
    const float* __restrict__ cPrevRow,      // global, this batch's row (H_)
    float* __restrict__ outH, float* __restrict__ outH2,
    float* __restrict__ outC,                // global, this batch's rows
    float* __restrict__ s_hout,              // smem h output (or nullptr)
    float* __restrict__ s_g)                 // smem gates [4*H_]
{
    // activation chunk for this lane (8 floats): lanes 0-15 -> x, 16-31 -> h
    const float* abase = (lane < 16) ? (sx + lane * 8) : (sh + (lane - 16) * 8);
    const float4 a0 = *reinterpret_cast<const float4*>(abase);
    const float4 a1 = *reinterpret_cast<const float4*>(abase + 4);

    #pragma unroll 2
    for (int j = warp; j < 4 * H_; j += 16) {
        const float* wbase = (lane < 16) ? (W_ih + j * H_ + lane * 8)
                                         : (W_hh + j * H_ + (lane - 16) * 8);
        const float4 w0 = *reinterpret_cast<const float4*>(wbase);
        const float4 w1 = *reinterpret_cast<const float4*>(wbase + 4);
        float acc = dot8_acc(w0, w1, a0, a1);
        acc = warp_sum(acc);
        if (lane == 0) s_g[j] = acc + b_ih[j] + b_hh[j];
    }
    __syncthreads();

    if (tid < H_) {
        const int h = tid;
        const float gi = s_g[h];
        const float gf = s_g[H_ + h];
        const float gg = s_g[2 * H_ + h];
        const float go = s_g[3 * H_ + h];
        const float cp = cPrevRow[h];
        const float cN = sigm(gf) * cp + sigm(gi) * tanhf(gg);
        const float hN = sigm(go) * tanhf(cN);
        outH[h] = hN;
        if (outH2) outH2[h] = hN;
        outC[h] = cN;
        if (s_hout) s_hout[h] = hN;
    }
    __syncthreads();
}

__global__ __launch_bounds__(512, 1)
void tail_batch_kernel(const float* __restrict__ input,
                       const float* __restrict__ h0,
                       const float* __restrict__ c0,
                       const float* __restrict__ inp_W,
                       const float* __restrict__ inp_b,
                       const float* __restrict__ W_ih0,
                       const float* __restrict__ W_hh0,
                       const float* __restrict__ b_ih0,
                       const float* __restrict__ b_hh0,
                       const float* __restrict__ W_ih1,
                       const float* __restrict__ W_hh1,
                       const float* __restrict__ b_ih1,
                       const float* __restrict__ b_hh1,
                       float* __restrict__ out)
{
    const int b    = blockIdx.x;
    const int tid  = threadIdx.x;
    const int warp = tid >> 5;
    const int lane = tid & 31;

    __shared__ __align__(16) float s_xcat[H_ + I_];
    __shared__ __align__(16) float s_h0a[H_];
    __shared__ __align__(16) float s_h0b[H_];
    __shared__ __align__(16) float s_xin[H_];
    __shared__ __align__(16) float s_h1[H_];
    __shared__ float s_g[4 * H_];

    // ---- Step A: softmax-combine + stage states (per-batch, no cross-block) ----
    if (tid < H_ + I_) {
        const int k = tid;
        if (k < H_) {
            float M = g_pm[b * CHUNKS + 0];
            #pragma unroll
            for (int cc = 1; cc < CHUNKS; cc++) M = fmaxf(M, g_pm[b * CHUNKS + cc]);
            float L = 0.f, A = 0.f;
            #pragma unroll
            for (int cc = 0; cc < CHUNKS; cc++) {
                const float e = __expf(g_pm[b * CHUNKS + cc] - M);
                L += g_pl[b * CHUNKS + cc] * e;
                A += g_pacc[(b * CHUNKS + cc) * H_ + k] * e;
            }
            s_xcat[k] = A / L;
            s_h0a[k] = h0[(0 * B_ + b) * H_ + k];
            s_h0b[k] = h0[(1 * B_ + b) * H_ + k];
        } else {
            s_xcat[k] = input[b * I_ + (k - H_)];
        }
    }
    __syncthreads();

    // ---- Step B: xin GEMV, warp-per-row (K = 256, 8 floats/lane) ----
    {
        const float4 a0 = *reinterpret_cast<const float4*>(s_xcat + lane * 8);
        const float4 a1 = *reinterpret_cast<const float4*>(s_xcat + lane * 8 + 4);
        #pragma unroll 2
        for (int j = warp; j < I_; j += 16) {
            const float* wbase = inp_W + j * (H_ + I_) + lane * 8;
            const float4 w0 = *reinterpret_cast<const float4*>(wbase);
            const float4 w1 = *reinterpret_cast<const float4*>(wbase + 4);
            float acc = dot8_acc(w0, w1, a0, a1);
            acc = warp_sum(acc);
            if (lane == 0) s_xin[j] = acc + inp_b[j];
        }
    }
    __syncthreads();

    // ---- Step C: LSTM layer 0 ----
    lstm_layer(tid, warp, lane, s_xin, s_h0a,
               W_ih0, W_hh0, b_ih0, b_hh0,
               c0 + (0 * B_ + b) * H_,
               out + 1 * B_ * H_ + b * H_, nullptr,
               out + 3 * B_ * H_ + b * H_,
               s_h1, s_g);

    // ---- Step D: LSTM layer 1 ----
    lstm_layer(tid, warp, lane, s_h1, s_h0b,
               W_ih1, W_hh1, b_ih1, b_hh1,
               c0 + (1 * B_ + b) * H_,
               out + 0 * B_ * H_ + b * H_, out + 2 * B_ * H_ + b * H_,
               out + 4 * B_ * H_ + b * H_,
               nullptr, s_g);
}

extern "C" void kernel_launch(void* const* d_in, const int* in_sizes, int n_in,
                              void* d_out, int out_size) {
    const float* input  = (const float*)d_in[0];
    const float* h0     = (const float*)d_in[1];
    const float* c0     = (const float*)d_in[2];
    const float* enc    = (const float*)d_in[3];
    const float* attW   = (const float*)d_in[4];
    const float* attB   = (const float*)d_in[5];
    const float* inp_W  = (const float*)d_in[6];
    const float* inp_b  = (const float*)d_in[7];
    const float* W_ih0  = (const float*)d_in[8];
    const float* W_hh0  = (const float*)d_in[9];
    const float* b_ih0  = (const float*)d_in[10];
    const float* b_hh0  = (const float*)d_in[11];
    const float* W_ih1  = (const float*)d_in[12];
    const float* W_hh1  = (const float*)d_in[13];
    const float* b_ih1  = (const float*)d_in[14];
    const float* b_hh1  = (const float*)d_in[15];
    float* out = (float*)d_out;

    dim3 grid1(CHUNKS, B_);
    attn_partial_kernel<<<grid1, 256>>>(enc, h0, c0, attW, attB);
    tail_batch_kernel<<<B_, 512>>>(input, h0, c0, inp_W, inp_b,
                                   W_ih0, W_hh0, b_ih0, b_hh0,
                                   W_ih1, W_hh1, b_ih1, b_hh1, out);
}